// round 16
// baseline (speedup 1.0000x reference)
#include <cuda_runtime.h>
#include <cuda_bf16.h>
#include <cstdint>
#include <cstddef>

#define BB 16
#define IC 8
#define OC 8
#define NV 3
#define HH 256
#define WW 256
#define M1 16
#define M2 16
#define TD 256

// -------------------- static scratch (no runtime allocation) --------------------
__device__ __align__(16) float2 g_Y[BB*IC*NV*HH*16];      // fwd DFT over w
__device__ __align__(16) float2 g_X[BB*IC*NV*32*16];      // fwd modes
__device__ __align__(16) float  g_TW[4*BB*(IC*OC*NV*M1*M2)]; // time-contracted weights
__device__ __align__(16) float  g_T5c[2048];              // [kw][w]: cos * al
__device__ __align__(16) float  g_T5s[2048];              // [kw][w]: sin * al
__device__ __align__(16) unsigned g_T1m[256*32];          // [w][c]: tf32 twiddles

__device__ __forceinline__ unsigned f2tf32(float f) {
    unsigned u;
    asm("cvt.rna.tf32.f32 %0, %1;" : "=r"(u) : "f"(f));
    return u;
}

// dynamic smem sizes
#define SMEM_K3A ((2*128*36 + 2*256*8) * 4)   // 53248 B
#define SMEM_K1  ((2*128*36 + 4*2048) * 4)    // 69632 B
// k45: CS tables 16*260 floats + Gs 512 float2 + Zs 256*17 float2
#define K45_CS_FLOATS (16 * 260)
#define SMEM_K45 ((K45_CS_FLOATS) * 4 + 512 * 8 + 256 * 17 * 8)   // 55552 B

// ---------------------------------------------------------------------------
// k0: twiddle tables, once per launch. 32 x 256 threads.
// ---------------------------------------------------------------------------
__global__ __launch_bounds__(256) void k0_tables() {
    const int idx = blockIdx.x * 256 + threadIdx.x;    // 0..8191
    if (idx < 2048) {
        int kw = idx >> 7, w = idx & 127;
        float sn, cs;
        sincospif((float)(kw * w) * (1.0f / 128.0f), &sn, &cs);
        float al = ((kw == 0) ? 1.0f : 2.0f) * (1.0f / 65536.0f);
        g_T5c[idx] = cs * al;
        g_T5s[idx] = sn * al;
    }
    {
        int w = idx >> 5, c = idx & 31;
        int k = c >> 1;
        float sn, cs;
        sincospif((float)(k * w) * (1.0f / 128.0f), &sn, &cs);
        g_T1m[idx] = f2tf32((c & 1) ? -sn : cs);
    }
}

// ---------------------------------------------------------------------------
// k1: forward DFT over w via tf32 MMA (r13 version, UNCHANGED). Grid 768.
// ---------------------------------------------------------------------------
__global__ __launch_bounds__(256) void k1_mma(const float* __restrict__ x) {
    extern __shared__ unsigned dsm1[];
    unsigned* WsA = dsm1;                 // [2][128*36]
    unsigned* TsA = dsm1 + 2 * 128 * 36;  // [4][2048]
    const int tid  = threadIdx.x;
    const int warp = tid >> 5;
    const int lane = tid & 31;
    const int g    = lane >> 2;
    const int tg   = lane & 3;
    const int row0 = blockIdx.x * 128;

#pragma unroll
    for (int j = 0; j < 32; j++) {
        int idx = j * 256 + tid;
        int w = idx >> 5, cc = idx & 31;
        TsA[(cc >> 3) * 2048 + w * 8 + (cc & 7)] = g_T1m[idx];
    }
#pragma unroll
    for (int j = 0; j < 4; j++) {
        int idx = j * 256 + tid;
        int rr = idx >> 3, q = idx & 7;
        float4 v = *(const float4*)(x + (size_t)(row0 + rr) * 256 + q * 4);
        unsigned* dst = &WsA[rr * 36 + q * 4];
        dst[0] = f2tf32(v.x); dst[1] = f2tf32(v.y);
        dst[2] = f2tf32(v.z); dst[3] = f2tf32(v.w);
    }
    __syncthreads();

    float d[4][4];
#pragma unroll
    for (int j = 0; j < 4; j++)
#pragma unroll
        for (int e = 0; e < 4; e++) d[j][e] = 0.0f;

#pragma unroll 1
    for (int c = 0; c < 8; c++) {
        float4 nv[4];
        if (c < 7) {
#pragma unroll
            for (int j = 0; j < 4; j++) {
                int idx = j * 256 + tid;
                int rr = idx >> 3, q = idx & 7;
                nv[j] = *(const float4*)(x + (size_t)(row0 + rr) * 256 + (c + 1) * 32 + q * 4);
            }
        }
        const unsigned* cw = WsA + (c & 1) * (128 * 36);
#pragma unroll
        for (int ks = 0; ks < 4; ks++) {
            const unsigned* ab = &cw[(warp * 16 + g) * 36 + ks * 8 + tg];
            unsigned a0 = ab[0];
            unsigned a1 = ab[8 * 36];
            unsigned a2 = ab[4];
            unsigned a3 = ab[8 * 36 + 4];
            int kg = c * 32 + ks * 8;
#pragma unroll
            for (int j = 0; j < 4; j++) {
                unsigned b0 = TsA[j * 2048 + (kg + tg) * 8 + g];
                unsigned b1 = TsA[j * 2048 + (kg + tg + 4) * 8 + g];
                asm volatile(
                    "mma.sync.aligned.m16n8k8.row.col.f32.tf32.tf32.f32 "
                    "{%0,%1,%2,%3}, {%4,%5,%6,%7}, {%8,%9}, {%0,%1,%2,%3};"
                    : "+f"(d[j][0]), "+f"(d[j][1]), "+f"(d[j][2]), "+f"(d[j][3])
                    : "r"(a0), "r"(a1), "r"(a2), "r"(a3), "r"(b0), "r"(b1));
            }
        }
        if (c < 7) {
            unsigned* nw = WsA + ((c + 1) & 1) * (128 * 36);
#pragma unroll
            for (int j = 0; j < 4; j++) {
                int idx = j * 256 + tid;
                int rr = idx >> 3, q = idx & 7;
                unsigned* dst = &nw[rr * 36 + q * 4];
                dst[0] = f2tf32(nv[j].x); dst[1] = f2tf32(nv[j].y);
                dst[2] = f2tf32(nv[j].z); dst[3] = f2tf32(nv[j].w);
            }
            __syncthreads();
        }
    }

    const int rowW = row0 + warp * 16;
#pragma unroll
    for (int j = 0; j < 4; j++) {
        int k = j * 4 + tg;
        g_Y[(size_t)(rowW + g)     * 16 + k] = make_float2(d[j][0], d[j][1]);
        g_Y[(size_t)(rowW + 8 + g) * 16 + k] = make_float2(d[j][2], d[j][3]);
    }
}

// ---------------------------------------------------------------------------
// k2: forward DFT over h (UNCHANGED). Grid 384 x 256.
// ---------------------------------------------------------------------------
__global__ __launch_bounds__(256) void k2_fwd_h() {
    __shared__ float2 sy[4096];   // [h][kw]
    const int tid = threadIdx.x;

    const float4* yg = (const float4*)(g_Y + (size_t)blockIdx.x * 4096);
    float4* sy4 = (float4*)sy;
#pragma unroll
    for (int it = 0; it < 8; it++)
        sy4[it * 256 + tid] = yg[it * 256 + tid];
    __syncthreads();

#pragma unroll
    for (int p = tid; p < 2048; p += 256) {
        int h = p >> 4, kw = p & 15;
        float2 a = sy[h * 16 + kw], b = sy[(h + 128) * 16 + kw];
        sy[h * 16 + kw]         = make_float2(a.x + b.x, a.y + b.y);
        sy[(h + 128) * 16 + kw] = make_float2(a.x - b.x, a.y - b.y);
    }
    __syncthreads();

    const int kw = tid & 15;
    const int s  = tid >> 4;
    const int hbase = (s & 1) << 7;

    float s1, c1, s2, c2;
    sincospif((float)s * (1.0f / 128.0f), &s1, &c1);
    sincospif((float)(s - 16) * (1.0f / 128.0f), &s2, &c2);
    const float st1c = c1, st1s = -s1;
    const float st2c = c2, st2s = -s2;
    float p1c = 1, p1s = 0, p2c = 1, p2s = 0;
    float a1r = 0, a1i = 0, a2r = 0, a2i = 0;

#pragma unroll 4
    for (int h = 0; h < 128; h++) {
        float2 u = sy[(hbase + h) * 16 + kw];
        a1r += u.x * p1c - u.y * p1s;
        a1i += u.x * p1s + u.y * p1c;
        a2r += u.x * p2c - u.y * p2s;
        a2i += u.x * p2s + u.y * p2c;
        float n;
        n = p1c * st1c - p1s * st1s; p1s = p1c * st1s + p1s * st1c; p1c = n;
        n = p2c * st2c - p2s * st2s; p2s = p2c * st2s + p2s * st2c; p2c = n;
    }

    size_t ob = (size_t)blockIdx.x * 512;
    g_X[ob + s * 16 + kw]        = make_float2(a1r, a1i);
    g_X[ob + (16 + s) * 16 + kw] = make_float2(a2r, a2i);
}

// ---------------------------------------------------------------------------
// k3a: time contraction via tf32 MMA (r13 version, UNCHANGED). Grid 1536.
// ---------------------------------------------------------------------------
__global__ __launch_bounds__(256) void k3a_time_mma(const float* __restrict__ t,
                                                    const float* __restrict__ wa,
                                                    const float* __restrict__ wb,
                                                    const float* __restrict__ wc,
                                                    const float* __restrict__ wd) {
    extern __shared__ unsigned dsm3[];
    unsigned* WsA  = dsm3;
    unsigned* tsB0 = dsm3 + 2 * 128 * 36;
    unsigned* tsB1 = tsB0 + 256 * 8;
    const int tid  = threadIdx.x;
    const int warp = tid >> 5;
    const int lane = tid & 31;
    const int g    = lane >> 2;
    const int tg   = lane & 3;

#pragma unroll
    for (int j = 0; j < 16; j++) {
        int idx = j * 256 + tid;
        int k = idx & 255, b = idx >> 8;
        unsigned v = f2tf32(t[b * 256 + k]);
        if (b < 8) tsB0[k * 8 + b] = v;
        else       tsB1[k * 8 + (b - 8)] = v;
    }

    const int arr  = blockIdx.x / 384;
    const int row0 = (blockIdx.x % 384) * 128;
    const float* W = (arr == 0) ? wa : (arr == 1) ? wb : (arr == 2) ? wc : wd;
    float* out = g_TW + (size_t)arr * (16 * 49152);

#pragma unroll
    for (int j = 0; j < 4; j++) {
        int idx = j * 256 + tid;
        int rr = idx >> 3, q = idx & 7;
        float4 v = *(const float4*)(W + (size_t)(row0 + rr) * 256 + q * 4);
        unsigned* dst = &WsA[rr * 36 + q * 4];
        dst[0] = f2tf32(v.x); dst[1] = f2tf32(v.y);
        dst[2] = f2tf32(v.z); dst[3] = f2tf32(v.w);
    }
    __syncthreads();

    float d0[2][4];
#pragma unroll
    for (int nt = 0; nt < 2; nt++)
#pragma unroll
        for (int e = 0; e < 4; e++) d0[nt][e] = 0.0f;

    const int rowW = row0 + warp * 16;

#pragma unroll 1
    for (int c = 0; c < 8; c++) {
        float4 nv[4];
        if (c < 7) {
#pragma unroll
            for (int j = 0; j < 4; j++) {
                int idx = j * 256 + tid;
                int rr = idx >> 3, q = idx & 7;
                nv[j] = *(const float4*)(W + (size_t)(row0 + rr) * 256 + (c + 1) * 32 + q * 4);
            }
        }
        const unsigned* cw = WsA + (c & 1) * (128 * 36);
#pragma unroll
        for (int ks = 0; ks < 4; ks++) {
            const unsigned* ab = &cw[(warp * 16 + g) * 36 + ks * 8 + tg];
            unsigned a0 = ab[0];
            unsigned a1 = ab[8 * 36];
            unsigned a2 = ab[4];
            unsigned a3 = ab[8 * 36 + 4];
            int kg = c * 32 + ks * 8;
            unsigned b00 = tsB0[(kg + tg) * 8 + g];
            unsigned b01 = tsB0[(kg + tg + 4) * 8 + g];
            unsigned b10 = tsB1[(kg + tg) * 8 + g];
            unsigned b11 = tsB1[(kg + tg + 4) * 8 + g];

            asm volatile(
                "mma.sync.aligned.m16n8k8.row.col.f32.tf32.tf32.f32 "
                "{%0,%1,%2,%3}, {%4,%5,%6,%7}, {%8,%9}, {%0,%1,%2,%3};"
                : "+f"(d0[0][0]), "+f"(d0[0][1]), "+f"(d0[0][2]), "+f"(d0[0][3])
                : "r"(a0), "r"(a1), "r"(a2), "r"(a3), "r"(b00), "r"(b01));
            asm volatile(
                "mma.sync.aligned.m16n8k8.row.col.f32.tf32.tf32.f32 "
                "{%0,%1,%2,%3}, {%4,%5,%6,%7}, {%8,%9}, {%0,%1,%2,%3};"
                : "+f"(d0[1][0]), "+f"(d0[1][1]), "+f"(d0[1][2]), "+f"(d0[1][3])
                : "r"(a0), "r"(a1), "r"(a2), "r"(a3), "r"(b10), "r"(b11));
        }
        if (c < 7) {
            unsigned* nw = WsA + ((c + 1) & 1) * (128 * 36);
#pragma unroll
            for (int j = 0; j < 4; j++) {
                int idx = j * 256 + tid;
                int rr = idx >> 3, q = idx & 7;
                unsigned* dst = &nw[rr * 36 + q * 4];
                dst[0] = f2tf32(nv[j].x); dst[1] = f2tf32(nv[j].y);
                dst[2] = f2tf32(nv[j].z); dst[3] = f2tf32(nv[j].w);
            }
            __syncthreads();
        }
    }

#pragma unroll
    for (int nt = 0; nt < 2; nt++) {
        int bb = nt * 8 + 2 * tg;
        out[(size_t)bb       * 49152 + rowW + g]     = d0[nt][0];
        out[(size_t)(bb + 1) * 49152 + rowW + g]     = d0[nt][1];
        out[(size_t)bb       * 49152 + rowW + 8 + g] = d0[nt][2];
        out[(size_t)(bb + 1) * 49152 + rowW + 8 + g] = d0[nt][3];
    }
}

// ---------------------------------------------------------------------------
// k45: FUSED mix + inv-h + inv-w. One block per (b,o,v): grid 384 x 512.
//   A: G[32][16] from g_X/g_TW (k3b math, one slot per thread)
//   B: inv-h DFT -> Zs[h][kw] smem, stride 17 (r8-verified body)
//   C: inv-w DFT -> out, tables in conflict-free smem layout
//      CS[wb*260 + kwv*16 + (0..7=cos, 8..15=sin)], 2-row pairing.
// ---------------------------------------------------------------------------
__global__ __launch_bounds__(512) void k45_fused(float* __restrict__ out) {
    extern __shared__ float dsm45[];
    float*  CS = dsm45;                          // 16*260 floats
    float2* Gs = (float2*)(dsm45 + K45_CS_FLOATS);        // 512
    float2* Zs = Gs + 512;                       // 256*17
    const int tid = threadIdx.x;
    const int bx  = blockIdx.x;                  // = (b*8+o)*3+v
    const int b   = bx / 24;
    const int o   = (bx % 24) / 3;
    const int v   = bx % 3;

    // stage tables into conflict-free layout
#pragma unroll
    for (int j = 0; j < 4; j++) {
        int idx = j * 512 + tid;                 // 0..2047
        int kwv = idx >> 7, w = idx & 127;
        int wb = w >> 3, u = w & 7;
        CS[wb * 260 + kwv * 16 + u]     = g_T5c[idx];
        CS[wb * 260 + kwv * 16 + 8 + u] = g_T5s[idx];
    }

    // ---- Stage A: spectral mixing over IC (one slot per thread) ----
    {
        const int kw = tid & 15;
        const int s  = tid >> 4;                 // 0..31
        const int arrbase = (s < 16) ? 0 : 2;
        const int y = s & 15;
        const float* TR = g_TW + (size_t)(arrbase * 16 + b) * 49152;
        const float* TI = g_TW + (size_t)((arrbase + 1) * 16 + b) * 49152;

        float gr = 0.0f, gi = 0.0f;
#pragma unroll
        for (int i = 0; i < 8; i++) {
            float2 xf = g_X[((size_t)((b * 8 + i) * 3 + v) * 32 + s) * 16 + kw];
            int row = (((i * 8 + o) * 3 + v) * 16 + y) * 16 + kw;
            float wr = TR[row], wi = TI[row];
            gr += xf.x * wr - xf.y * wi;
            gi += xf.x * wi + xf.y * wr;
        }
        Gs[s * 16 + kw] = make_float2(gr, gi);
    }
    __syncthreads();

    // ---- Stage B: inverse DFT over h (r8-verified; Zs stride 17) ----
    {
        const int h   = tid & 127;
        const int kwq = tid >> 7;                // 4 kw per thread

        float AR[4], AI[4], BR[4], BI[4];
#pragma unroll
        for (int q = 0; q < 4; q++) { AR[q] = AI[q] = BR[q] = BI[q] = 0.0f; }

        float stc, sts;
        sincospif((float)h * (1.0f / 128.0f), &sts, &stc);   // e^{+2pi i h/256}
        float pc = 1.0f, ps = 0.0f;

#pragma unroll 1
        for (int sl = 0; sl < 32; sl++) {
            if (sl == 16) { ps = -ps; }          // kh jumps to 240 == -16
            const float2* gp = &Gs[sl * 16 + kwq * 4];
            if ((sl & 1) == 0) {
#pragma unroll
                for (int q = 0; q < 4; q++) {
                    float2 g = gp[q];
                    AR[q] += g.x * pc - g.y * ps;
                    AI[q] += g.x * ps + g.y * pc;
                }
            } else {
#pragma unroll
                for (int q = 0; q < 4; q++) {
                    float2 g = gp[q];
                    BR[q] += g.x * pc - g.y * ps;
                    BI[q] += g.x * ps + g.y * pc;
                }
            }
            float n = pc * stc - ps * sts;
            ps = pc * sts + ps * stc; pc = n;
        }

        float2* zlo = &Zs[h * 17 + kwq * 4];
        float2* zhi = &Zs[(h + 128) * 17 + kwq * 4];
#pragma unroll
        for (int q = 0; q < 4; q++) {
            zlo[q] = make_float2(AR[q] + BR[q], AI[q] + BI[q]);
            zhi[q] = make_float2(AR[q] - BR[q], AI[q] - BI[q]);
        }
    }
    __syncthreads();

    // ---- Stage C: inverse real DFT over w, conflict-free tables, 2-row pairs ----
    float* obase = out + (size_t)bx * 65536;
    const int r0 = tid >> 4;                     // 0..31
    const int wb = tid & 15;                     // w = wb*8 + u
    const float* myCS = CS + wb * 260;

#pragma unroll 1
    for (int rep = 0; rep < 4; rep++) {
        const int r = rep * 64 + r0;             // rows r and r+32

        float A0[8], B0[8], A1[8], B1[8];
#pragma unroll
        for (int u = 0; u < 8; u++) { A0[u] = B0[u] = A1[u] = B1[u] = 0.0f; }

#pragma unroll
        for (int kwv = 0; kwv < 16; kwv++) {
            float2 z0 = Zs[r * 17 + kwv];
            float2 z1 = Zs[(r + 32) * 17 + kwv];
            float4 c0 = *(const float4*)&myCS[kwv * 16];
            float4 c1 = *(const float4*)&myCS[kwv * 16 + 4];
            float4 s0 = *(const float4*)&myCS[kwv * 16 + 8];
            float4 s1 = *(const float4*)&myCS[kwv * 16 + 12];
            float ce[8] = {c0.x, c0.y, c0.z, c0.w, c1.x, c1.y, c1.z, c1.w};
            float se[8] = {s0.x, s0.y, s0.z, s0.w, s1.x, s1.y, s1.z, s1.w};
            float* T0 = ((kwv & 1) == 0) ? A0 : B0;
            float* T1 = ((kwv & 1) == 0) ? A1 : B1;
#pragma unroll
            for (int u = 0; u < 8; u++) {
                T0[u] += z0.x * ce[u] - z0.y * se[u];
                T1[u] += z1.x * ce[u] - z1.y * se[u];
            }
        }

        float* orow0 = obase + (size_t)r * 256 + wb * 8;
        float* orow1 = obase + (size_t)(r + 32) * 256 + wb * 8;
#pragma unroll
        for (int u4 = 0; u4 < 2; u4++) {
            float4 lo0 = make_float4(A0[u4*4+0] + B0[u4*4+0], A0[u4*4+1] + B0[u4*4+1],
                                     A0[u4*4+2] + B0[u4*4+2], A0[u4*4+3] + B0[u4*4+3]);
            float4 hi0 = make_float4(A0[u4*4+0] - B0[u4*4+0], A0[u4*4+1] - B0[u4*4+1],
                                     A0[u4*4+2] - B0[u4*4+2], A0[u4*4+3] - B0[u4*4+3]);
            float4 lo1 = make_float4(A1[u4*4+0] + B1[u4*4+0], A1[u4*4+1] + B1[u4*4+1],
                                     A1[u4*4+2] + B1[u4*4+2], A1[u4*4+3] + B1[u4*4+3]);
            float4 hi1 = make_float4(A1[u4*4+0] - B1[u4*4+0], A1[u4*4+1] - B1[u4*4+1],
                                     A1[u4*4+2] - B1[u4*4+2], A1[u4*4+3] - B1[u4*4+3]);
            *(float4*)&orow0[u4 * 4]       = lo0;
            *(float4*)&orow0[128 + u4 * 4] = hi0;
            *(float4*)&orow1[u4 * 4]       = lo1;
            *(float4*)&orow1[128 + u4 * 4] = hi1;
        }
    }
}

// ---------------------------------------------------------------------------
extern "C" void kernel_launch(void* const* d_in, const int* in_sizes, int n_in,
                              void* d_out, int out_size) {
    const float* t = nullptr;
    const float* x = nullptr;
    const float* w[4] = {nullptr, nullptr, nullptr, nullptr};
    int wn = 0;
    for (int i = 0; i < n_in; i++) {
        if (in_sizes[i] == BB * TD)                      t = (const float*)d_in[i];
        else if (in_sizes[i] == BB * IC * NV * HH * WW)  x = (const float*)d_in[i];
        else if (wn < 4)                                 w[wn++] = (const float*)d_in[i];
    }
    float* out = (float*)d_out;

    cudaFuncSetAttribute(k1_mma, cudaFuncAttributeMaxDynamicSharedMemorySize, SMEM_K1);
    cudaFuncSetAttribute(k3a_time_mma, cudaFuncAttributeMaxDynamicSharedMemorySize, SMEM_K3A);
    cudaFuncSetAttribute(k45_fused, cudaFuncAttributeMaxDynamicSharedMemorySize, SMEM_K45);

    k0_tables<<<32, 256>>>();
    k1_mma<<<768, 256, SMEM_K1>>>(x);
    k2_fwd_h<<<384, 256>>>();
    k3a_time_mma<<<1536, 256, SMEM_K3A>>>(t, w[0], w[1], w[2], w[3]);
    k45_fused<<<384, 512, SMEM_K45>>>(out);
}

// round 17
// speedup vs baseline: 2.4995x; 2.4995x over previous
#include <cuda_runtime.h>
#include <cuda_bf16.h>
#include <cstdint>
#include <cstddef>

#define BB 16
#define IC 8
#define OC 8
#define NV 3
#define HH 256
#define WW 256
#define M1 16
#define M2 16
#define TD 256

// -------------------- static scratch (no runtime allocation) --------------------
__device__ __align__(16) float2 g_Y[BB*IC*NV*HH*16];      // fwd DFT over w
__device__ __align__(16) float2 g_X[BB*IC*NV*32*16];      // fwd modes
__device__ __align__(16) float  g_TW[4*BB*(IC*OC*NV*M1*M2)]; // time-contracted weights
__device__ __align__(16) float2 g_Z[BB*OC*NV*HH*16];      // inv DFT over h
__device__ __align__(16) float  g_T5c[2048];              // [kw][w]: cos * al
__device__ __align__(16) float  g_T5s[2048];              // [kw][w]: sin * al
__device__ __align__(16) unsigned g_T1m[256*32];          // [w][c]: tf32 twiddles

__device__ __forceinline__ unsigned f2tf32(float f) {
    unsigned u;
    asm("cvt.rna.tf32.f32 %0, %1;" : "=r"(u) : "f"(f));
    return u;
}

// dynamic smem sizes
#define SMEM_K3A ((2*128*36 + 2*256*8) * 4)   // 53248 B
#define SMEM_K1  ((2*128*36 + 4*2048) * 4)    // 69632 B

// ---------------------------------------------------------------------------
// k0: twiddle tables, once per launch. 32 x 256 threads.
// ---------------------------------------------------------------------------
__global__ __launch_bounds__(256) void k0_tables() {
    const int idx = blockIdx.x * 256 + threadIdx.x;    // 0..8191
    if (idx < 2048) {
        int kw = idx >> 7, w = idx & 127;
        float sn, cs;
        sincospif((float)(kw * w) * (1.0f / 128.0f), &sn, &cs);
        float al = ((kw == 0) ? 1.0f : 2.0f) * (1.0f / 65536.0f);
        g_T5c[idx] = cs * al;
        g_T5s[idx] = sn * al;
    }
    {
        int w = idx >> 5, c = idx & 31;
        int k = c >> 1;
        float sn, cs;
        sincospif((float)(k * w) * (1.0f / 128.0f), &sn, &cs);
        g_T1m[idx] = f2tf32((c & 1) ? -sn : cs);
    }
}

// ---------------------------------------------------------------------------
// k1: forward DFT over w via tf32 MMA (r13 version, UNCHANGED). Grid 768.
// ---------------------------------------------------------------------------
__global__ __launch_bounds__(256) void k1_mma(const float* __restrict__ x) {
    extern __shared__ unsigned dsm1[];
    unsigned* WsA = dsm1;                 // [2][128*36]
    unsigned* TsA = dsm1 + 2 * 128 * 36;  // [4][2048]
    const int tid  = threadIdx.x;
    const int warp = tid >> 5;
    const int lane = tid & 31;
    const int g    = lane >> 2;
    const int tg   = lane & 3;
    const int row0 = blockIdx.x * 128;

#pragma unroll
    for (int j = 0; j < 32; j++) {
        int idx = j * 256 + tid;
        int w = idx >> 5, cc = idx & 31;
        TsA[(cc >> 3) * 2048 + w * 8 + (cc & 7)] = g_T1m[idx];
    }
#pragma unroll
    for (int j = 0; j < 4; j++) {
        int idx = j * 256 + tid;
        int rr = idx >> 3, q = idx & 7;
        float4 v = *(const float4*)(x + (size_t)(row0 + rr) * 256 + q * 4);
        unsigned* dst = &WsA[rr * 36 + q * 4];
        dst[0] = f2tf32(v.x); dst[1] = f2tf32(v.y);
        dst[2] = f2tf32(v.z); dst[3] = f2tf32(v.w);
    }
    __syncthreads();

    float d[4][4];
#pragma unroll
    for (int j = 0; j < 4; j++)
#pragma unroll
        for (int e = 0; e < 4; e++) d[j][e] = 0.0f;

#pragma unroll 1
    for (int c = 0; c < 8; c++) {
        float4 nv[4];
        if (c < 7) {
#pragma unroll
            for (int j = 0; j < 4; j++) {
                int idx = j * 256 + tid;
                int rr = idx >> 3, q = idx & 7;
                nv[j] = *(const float4*)(x + (size_t)(row0 + rr) * 256 + (c + 1) * 32 + q * 4);
            }
        }
        const unsigned* cw = WsA + (c & 1) * (128 * 36);
#pragma unroll
        for (int ks = 0; ks < 4; ks++) {
            const unsigned* ab = &cw[(warp * 16 + g) * 36 + ks * 8 + tg];
            unsigned a0 = ab[0];
            unsigned a1 = ab[8 * 36];
            unsigned a2 = ab[4];
            unsigned a3 = ab[8 * 36 + 4];
            int kg = ks * 8;
#pragma unroll
            for (int j = 0; j < 4; j++) {
                unsigned b0 = TsA[j * 2048 + (c * 32 + kg + tg) * 8 + g];
                unsigned b1 = TsA[j * 2048 + (c * 32 + kg + tg + 4) * 8 + g];
                asm volatile(
                    "mma.sync.aligned.m16n8k8.row.col.f32.tf32.tf32.f32 "
                    "{%0,%1,%2,%3}, {%4,%5,%6,%7}, {%8,%9}, {%0,%1,%2,%3};"
                    : "+f"(d[j][0]), "+f"(d[j][1]), "+f"(d[j][2]), "+f"(d[j][3])
                    : "r"(a0), "r"(a1), "r"(a2), "r"(a3), "r"(b0), "r"(b1));
            }
        }
        if (c < 7) {
            unsigned* nw = WsA + ((c + 1) & 1) * (128 * 36);
#pragma unroll
            for (int j = 0; j < 4; j++) {
                int idx = j * 256 + tid;
                int rr = idx >> 3, q = idx & 7;
                unsigned* dst = &nw[rr * 36 + q * 4];
                dst[0] = f2tf32(nv[j].x); dst[1] = f2tf32(nv[j].y);
                dst[2] = f2tf32(nv[j].z); dst[3] = f2tf32(nv[j].w);
            }
            __syncthreads();
        }
    }

    const int rowW = row0 + warp * 16;
#pragma unroll
    for (int j = 0; j < 4; j++) {
        int k = j * 4 + tg;
        g_Y[(size_t)(rowW + g)     * 16 + k] = make_float2(d[j][0], d[j][1]);
        g_Y[(size_t)(rowW + 8 + g) * 16 + k] = make_float2(d[j][2], d[j][3]);
    }
}

// ---------------------------------------------------------------------------
// k2: forward DFT over h (UNCHANGED). Grid 384 x 256.
// ---------------------------------------------------------------------------
__global__ __launch_bounds__(256) void k2_fwd_h() {
    __shared__ float2 sy[4096];   // [h][kw]
    const int tid = threadIdx.x;

    const float4* yg = (const float4*)(g_Y + (size_t)blockIdx.x * 4096);
    float4* sy4 = (float4*)sy;
#pragma unroll
    for (int it = 0; it < 8; it++)
        sy4[it * 256 + tid] = yg[it * 256 + tid];
    __syncthreads();

#pragma unroll
    for (int p = tid; p < 2048; p += 256) {
        int h = p >> 4, kw = p & 15;
        float2 a = sy[h * 16 + kw], b = sy[(h + 128) * 16 + kw];
        sy[h * 16 + kw]         = make_float2(a.x + b.x, a.y + b.y);
        sy[(h + 128) * 16 + kw] = make_float2(a.x - b.x, a.y - b.y);
    }
    __syncthreads();

    const int kw = tid & 15;
    const int s  = tid >> 4;
    const int hbase = (s & 1) << 7;

    float s1, c1, s2, c2;
    sincospif((float)s * (1.0f / 128.0f), &s1, &c1);
    sincospif((float)(s - 16) * (1.0f / 128.0f), &s2, &c2);
    const float st1c = c1, st1s = -s1;
    const float st2c = c2, st2s = -s2;
    float p1c = 1, p1s = 0, p2c = 1, p2s = 0;
    float a1r = 0, a1i = 0, a2r = 0, a2i = 0;

#pragma unroll 4
    for (int h = 0; h < 128; h++) {
        float2 u = sy[(hbase + h) * 16 + kw];
        a1r += u.x * p1c - u.y * p1s;
        a1i += u.x * p1s + u.y * p1c;
        a2r += u.x * p2c - u.y * p2s;
        a2i += u.x * p2s + u.y * p2c;
        float n;
        n = p1c * st1c - p1s * st1s; p1s = p1c * st1s + p1s * st1c; p1c = n;
        n = p2c * st2c - p2s * st2s; p2s = p2c * st2s + p2s * st2c; p2c = n;
    }

    size_t ob = (size_t)blockIdx.x * 512;
    g_X[ob + s * 16 + kw]        = make_float2(a1r, a1i);
    g_X[ob + (16 + s) * 16 + kw] = make_float2(a2r, a2i);
}

// ---------------------------------------------------------------------------
// k3a: time contraction via tf32 MMA (r13 version, UNCHANGED). Grid 1536.
// ---------------------------------------------------------------------------
__global__ __launch_bounds__(256) void k3a_time_mma(const float* __restrict__ t,
                                                    const float* __restrict__ wa,
                                                    const float* __restrict__ wb,
                                                    const float* __restrict__ wc,
                                                    const float* __restrict__ wd) {
    extern __shared__ unsigned dsm3[];
    unsigned* WsA  = dsm3;
    unsigned* tsB0 = dsm3 + 2 * 128 * 36;
    unsigned* tsB1 = tsB0 + 256 * 8;
    const int tid  = threadIdx.x;
    const int warp = tid >> 5;
    const int lane = tid & 31;
    const int g    = lane >> 2;
    const int tg   = lane & 3;

#pragma unroll
    for (int j = 0; j < 16; j++) {
        int idx = j * 256 + tid;
        int k = idx & 255, b = idx >> 8;
        unsigned v = f2tf32(t[b * 256 + k]);
        if (b < 8) tsB0[k * 8 + b] = v;
        else       tsB1[k * 8 + (b - 8)] = v;
    }

    const int arr  = blockIdx.x / 384;
    const int row0 = (blockIdx.x % 384) * 128;
    const float* W = (arr == 0) ? wa : (arr == 1) ? wb : (arr == 2) ? wc : wd;
    float* out = g_TW + (size_t)arr * (16 * 49152);

#pragma unroll
    for (int j = 0; j < 4; j++) {
        int idx = j * 256 + tid;
        int rr = idx >> 3, q = idx & 7;
        float4 v = *(const float4*)(W + (size_t)(row0 + rr) * 256 + q * 4);
        unsigned* dst = &WsA[rr * 36 + q * 4];
        dst[0] = f2tf32(v.x); dst[1] = f2tf32(v.y);
        dst[2] = f2tf32(v.z); dst[3] = f2tf32(v.w);
    }
    __syncthreads();

    float d0[2][4];
#pragma unroll
    for (int nt = 0; nt < 2; nt++)
#pragma unroll
        for (int e = 0; e < 4; e++) d0[nt][e] = 0.0f;

    const int rowW = row0 + warp * 16;

#pragma unroll 1
    for (int c = 0; c < 8; c++) {
        float4 nv[4];
        if (c < 7) {
#pragma unroll
            for (int j = 0; j < 4; j++) {
                int idx = j * 256 + tid;
                int rr = idx >> 3, q = idx & 7;
                nv[j] = *(const float4*)(W + (size_t)(row0 + rr) * 256 + (c + 1) * 32 + q * 4);
            }
        }
        const unsigned* cw = WsA + (c & 1) * (128 * 36);
#pragma unroll
        for (int ks = 0; ks < 4; ks++) {
            const unsigned* ab = &cw[(warp * 16 + g) * 36 + ks * 8 + tg];
            unsigned a0 = ab[0];
            unsigned a1 = ab[8 * 36];
            unsigned a2 = ab[4];
            unsigned a3 = ab[8 * 36 + 4];
            int kg = c * 32 + ks * 8;
            unsigned b00 = tsB0[(kg + tg) * 8 + g];
            unsigned b01 = tsB0[(kg + tg + 4) * 8 + g];
            unsigned b10 = tsB1[(kg + tg) * 8 + g];
            unsigned b11 = tsB1[(kg + tg + 4) * 8 + g];

            asm volatile(
                "mma.sync.aligned.m16n8k8.row.col.f32.tf32.tf32.f32 "
                "{%0,%1,%2,%3}, {%4,%5,%6,%7}, {%8,%9}, {%0,%1,%2,%3};"
                : "+f"(d0[0][0]), "+f"(d0[0][1]), "+f"(d0[0][2]), "+f"(d0[0][3])
                : "r"(a0), "r"(a1), "r"(a2), "r"(a3), "r"(b00), "r"(b01));
            asm volatile(
                "mma.sync.aligned.m16n8k8.row.col.f32.tf32.tf32.f32 "
                "{%0,%1,%2,%3}, {%4,%5,%6,%7}, {%8,%9}, {%0,%1,%2,%3};"
                : "+f"(d0[1][0]), "+f"(d0[1][1]), "+f"(d0[1][2]), "+f"(d0[1][3])
                : "r"(a0), "r"(a1), "r"(a2), "r"(a3), "r"(b10), "r"(b11));
        }
        if (c < 7) {
            unsigned* nw = WsA + ((c + 1) & 1) * (128 * 36);
#pragma unroll
            for (int j = 0; j < 4; j++) {
                int idx = j * 256 + tid;
                int rr = idx >> 3, q = idx & 7;
                unsigned* dst = &nw[rr * 36 + q * 4];
                dst[0] = f2tf32(nv[j].x); dst[1] = f2tf32(nv[j].y);
                dst[2] = f2tf32(nv[j].z); dst[3] = f2tf32(nv[j].w);
            }
            __syncthreads();
        }
    }

#pragma unroll
    for (int nt = 0; nt < 2; nt++) {
        int bb = nt * 8 + 2 * tg;
        out[(size_t)bb       * 49152 + rowW + g]     = d0[nt][0];
        out[(size_t)(bb + 1) * 49152 + rowW + g]     = d0[nt][1];
        out[(size_t)bb       * 49152 + rowW + 8 + g] = d0[nt][2];
        out[(size_t)(bb + 1) * 49152 + rowW + 8 + g] = d0[nt][3];
    }
}

// ---------------------------------------------------------------------------
// k4: fused spectral mix + inverse DFT over h (r13 version, UNCHANGED).
// ---------------------------------------------------------------------------
__global__ __launch_bounds__(256) void k4_fused() {
    __shared__ float2 Gs[512];
    const int tid = threadIdx.x;
    const int bx  = blockIdx.x;
    const int b   = bx / 24;
    const int o   = (bx % 24) / 3;
    const int v   = bx % 3;

    {
        const int kw = tid & 15;
        const int s1 = tid >> 4;
        const float* TR1 = g_TW + (size_t)(0 * 16 + b) * 49152;
        const float* TI1 = g_TW + (size_t)(1 * 16 + b) * 49152;
        const float* TR2 = g_TW + (size_t)(2 * 16 + b) * 49152;
        const float* TI2 = g_TW + (size_t)(3 * 16 + b) * 49152;

        float g1r = 0, g1i = 0, g2r = 0, g2i = 0;
#pragma unroll
        for (int i = 0; i < 8; i++) {
            size_t xb = (size_t)((b * 8 + i) * 3 + v) * 512 + kw;
            float2 x1 = g_X[xb + s1 * 16];
            float2 x2 = g_X[xb + (16 + s1) * 16];
            int row = (((i * 8 + o) * 3 + v) * 16 + s1) * 16 + kw;
            float w1r = TR1[row], w1i = TI1[row];
            float w2r = TR2[row], w2i = TI2[row];
            g1r += x1.x * w1r - x1.y * w1i;
            g1i += x1.x * w1i + x1.y * w1r;
            g2r += x2.x * w2r - x2.y * w2i;
            g2i += x2.x * w2i + x2.y * w2r;
        }
        Gs[s1 * 16 + kw]        = make_float2(g1r, g1i);
        Gs[(16 + s1) * 16 + kw] = make_float2(g2r, g2i);
    }
    __syncthreads();

    const int h = tid & 127;
    const int half = tid >> 7;

    float AR[8], AI[8], BR[8], BI[8];
#pragma unroll
    for (int q = 0; q < 8; q++) { AR[q] = AI[q] = BR[q] = BI[q] = 0.0f; }

    float stc, sts;
    sincospif((float)h * (1.0f / 128.0f), &sts, &stc);
    float pc = 1.0f, ps = 0.0f;

#pragma unroll 1
    for (int sl = 0; sl < 32; sl++) {
        if (sl == 16) { ps = -ps; }
        const float4* gp = (const float4*)&Gs[sl * 16 + half * 8];
        if ((sl & 1) == 0) {
#pragma unroll
            for (int q4 = 0; q4 < 4; q4++) {
                float4 g = gp[q4];
                AR[2*q4]   += g.x * pc - g.y * ps;
                AI[2*q4]   += g.x * ps + g.y * pc;
                AR[2*q4+1] += g.z * pc - g.w * ps;
                AI[2*q4+1] += g.z * ps + g.w * pc;
            }
        } else {
#pragma unroll
            for (int q4 = 0; q4 < 4; q4++) {
                float4 g = gp[q4];
                BR[2*q4]   += g.x * pc - g.y * ps;
                BI[2*q4]   += g.x * ps + g.y * pc;
                BR[2*q4+1] += g.z * pc - g.w * ps;
                BI[2*q4+1] += g.z * ps + g.w * pc;
            }
        }
        float n = pc * stc - ps * sts;
        ps = pc * sts + ps * stc; pc = n;
    }

    float4* zlo = (float4*)(g_Z + (size_t)bx * 4096 + h * 16 + half * 8);
    float4* zhi = (float4*)(g_Z + (size_t)bx * 4096 + (h + 128) * 16 + half * 8);
#pragma unroll
    for (int q = 0; q < 4; q++) {
        zlo[q] = make_float4(AR[2*q] + BR[2*q], AI[2*q] + BI[2*q],
                             AR[2*q+1] + BR[2*q+1], AI[2*q+1] + BI[2*q+1]);
        zhi[q] = make_float4(AR[2*q] - BR[2*q], AI[2*q] - BI[2*q],
                             AR[2*q+1] - BR[2*q+1], AI[2*q+1] - BI[2*q+1]);
    }
}

// ---------------------------------------------------------------------------
// k5: inverse real DFT over w — r12 grid/mapping (3072 blocks, 32 rows,
// 256 threads), but CONFLICT-FREE smem layouts:
//   tables: CS[wb*516 + kwv*32 + u (cos) / +16+u (sin)]  (wb stride == 4 mod 32)
//   Zs: stride 17 float2 (banks r*2, distinct per warp)
// ---------------------------------------------------------------------------
__global__ __launch_bounds__(256) void k5_inv_w(float* __restrict__ out) {
    __shared__ float  CS[8 * 516];        // 16.1 KB
    __shared__ float2 Zs[32 * 17];        // 4.3 KB
    const int tid = threadIdx.x;

    // stage tables into conflict-free layout (2048 entries each)
#pragma unroll
    for (int j = 0; j < 8; j++) {
        int idx = j * 256 + tid;          // 0..2047
        int kwv = idx >> 7, w = idx & 127;
        int wb = w >> 4, u = w & 15;
        CS[wb * 516 + kwv * 32 + u]      = g_T5c[idx];
        CS[wb * 516 + kwv * 32 + 16 + u] = g_T5s[idx];
    }
    // stage Z with stride 17
#pragma unroll
    for (int j = 0; j < 2; j++) {
        int idx = j * 256 + tid;          // 0..511
        int r = idx >> 4, kwv = idx & 15;
        Zs[r * 17 + kwv] = g_Z[(size_t)blockIdx.x * 512 + idx];
    }
    __syncthreads();

    const int r  = tid >> 3;    // 0..31
    const int wb = tid & 7;     // w chunk: w = wb*16 + u
    const float* myCS = CS + wb * 516;

    float A[16], B[16];
#pragma unroll
    for (int u = 0; u < 16; u++) { A[u] = 0.0f; B[u] = 0.0f; }

#pragma unroll
    for (int kwv = 0; kwv < 16; kwv++) {
        float2 z = Zs[r * 17 + kwv];
#pragma unroll
        for (int u4 = 0; u4 < 4; u4++) {
            float4 c4 = *(const float4*)&myCS[kwv * 32 + u4 * 4];
            float4 s4 = *(const float4*)&myCS[kwv * 32 + 16 + u4 * 4];
            float* T = ((kwv & 1) == 0) ? A : B;
            T[u4 * 4 + 0] += z.x * c4.x - z.y * s4.x;
            T[u4 * 4 + 1] += z.x * c4.y - z.y * s4.y;
            T[u4 * 4 + 2] += z.x * c4.z - z.y * s4.z;
            T[u4 * 4 + 3] += z.x * c4.w - z.y * s4.w;
        }
    }

    float* orow = out + (size_t)blockIdx.x * (32 * 256) + r * 256 + wb * 16;
#pragma unroll
    for (int u4 = 0; u4 < 4; u4++) {
        float4 lo = make_float4(A[u4*4+0] + B[u4*4+0], A[u4*4+1] + B[u4*4+1],
                                A[u4*4+2] + B[u4*4+2], A[u4*4+3] + B[u4*4+3]);
        float4 hi = make_float4(A[u4*4+0] - B[u4*4+0], A[u4*4+1] - B[u4*4+1],
                                A[u4*4+2] - B[u4*4+2], A[u4*4+3] - B[u4*4+3]);
        *(float4*)&orow[u4 * 4]       = lo;
        *(float4*)&orow[128 + u4 * 4] = hi;
    }
}

// ---------------------------------------------------------------------------
extern "C" void kernel_launch(void* const* d_in, const int* in_sizes, int n_in,
                              void* d_out, int out_size) {
    const float* t = nullptr;
    const float* x = nullptr;
    const float* w[4] = {nullptr, nullptr, nullptr, nullptr};
    int wn = 0;
    for (int i = 0; i < n_in; i++) {
        if (in_sizes[i] == BB * TD)                      t = (const float*)d_in[i];
        else if (in_sizes[i] == BB * IC * NV * HH * WW)  x = (const float*)d_in[i];
        else if (wn < 4)                                 w[wn++] = (const float*)d_in[i];
    }
    float* out = (float*)d_out;

    cudaFuncSetAttribute(k1_mma, cudaFuncAttributeMaxDynamicSharedMemorySize, SMEM_K1);
    cudaFuncSetAttribute(k3a_time_mma, cudaFuncAttributeMaxDynamicSharedMemorySize, SMEM_K3A);

    k0_tables<<<32, 256>>>();
    k1_mma<<<768, 256, SMEM_K1>>>(x);
    k2_fwd_h<<<384, 256>>>();
    k3a_time_mma<<<1536, 256, SMEM_K3A>>>(t, w[0], w[1], w[2], w[3]);
    k4_fused<<<384, 256>>>();
    k5_inv_w<<<3072, 256>>>(out);
}